// round 15
// baseline (speedup 1.0000x reference)
#include <cuda_runtime.h>
#include <cuda_fp16.h>
#include <cstdint>

constexpr int NA = 1024, NB = 1024, DD = 512, KK = 256;
constexpr unsigned int GRID = 128;

// Device scratch
__device__ __half g_Xh[(NA + NB) * DD];
__device__ __half g_Fh[KK * DD];
__device__ __half g_Ph[NA * KK];
__device__ __half g_Mb[NB * KK];

// Monotonic dataflow flags (never reset; targets derived from runid)
__device__ unsigned int g_run;        // CTA arrival counter -> runid
__device__ int g_cvtX[32];            // per 64-row X tile: 4 producers
__device__ int g_cvtF[4];             // per 64-row F tile: 32 producers
__device__ int g_rdyP[16];            // per 64-row Ph tile: 4 producers
__device__ int g_rdyM[16];            // per 64-row Mb tile: 4 producers

constexpr float FIXTHR = 0.25f;
constexpr int LFIXMAX = 512;

// ---------------------------------------------------------------------------
__device__ __forceinline__ uint32_t smem_u32(const void* p) {
    uint32_t r;
    asm("{ .reg .u64 t; cvta.to.shared.u64 t, %1; cvt.u32.u64 %0, t; }" : "=r"(r) : "l"(p));
    return r;
}
__device__ __forceinline__ void cp16(uint32_t dst, const void* src) {
    asm volatile("cp.async.cg.shared.global [%0], [%1], 16;" :: "r"(dst), "l"(src) : "memory");
}
__device__ __forceinline__ void cp_commit() { asm volatile("cp.async.commit_group;" ::: "memory"); }
__device__ __forceinline__ void cp_wait1()  { asm volatile("cp.async.wait_group 1;" ::: "memory"); }
__device__ __forceinline__ void cp_wait0()  { asm volatile("cp.async.wait_group 0;" ::: "memory"); }

__device__ __forceinline__ void ldm_x4(uint32_t* r, uint32_t addr) {
    asm volatile("ldmatrix.sync.aligned.m8n8.x4.shared.b16 {%0,%1,%2,%3}, [%4];"
                 : "=r"(r[0]), "=r"(r[1]), "=r"(r[2]), "=r"(r[3]) : "r"(addr));
}
__device__ __forceinline__ void mma_f16(float* d, const uint32_t* a, const uint32_t* b) {
    asm volatile(
        "mma.sync.aligned.m16n8k16.row.col.f32.f16.f16.f32 "
        "{%0,%1,%2,%3}, {%4,%5,%6,%7}, {%8,%9}, {%0,%1,%2,%3};"
        : "+f"(d[0]), "+f"(d[1]), "+f"(d[2]), "+f"(d[3])
        : "r"(a[0]), "r"(a[1]), "r"(a[2]), "r"(a[3]), "r"(b[0]), "r"(b[1]));
}

constexpr uint32_t TSTR = 144;
constexpr uint32_t ARR  = 64 * TSTR;   // 9216

__device__ __forceinline__ uint32_t a_addr(uint32_t base, int row0, int lane, int koff) {
    return base + (uint32_t)(row0 + (lane & 15)) * TSTR + (uint32_t)koff + ((lane >> 4) << 4);
}
__device__ __forceinline__ uint32_t b_addr(uint32_t base, int row0, int lane, int koff) {
    return base + (uint32_t)(row0 + (lane & 7) + ((lane >> 4) << 3)) * TSTR
                + (uint32_t)koff + (((lane >> 3) & 1) << 4);
}

__device__ __forceinline__ int ld_acq(const int* p) {
    int v;
    asm volatile("ld.acquire.gpu.s32 %0, [%1];" : "=r"(v) : "l"(p));
    return v;
}

__device__ __forceinline__ uint32_t hpack(float x, float y) {
    __half2 t = __float22half2_rn(make_float2(x, y));
    return *reinterpret_cast<uint32_t*>(&t);
}
__device__ __forceinline__ uint4 hi4(const float4& v0, const float4& v1) {
    return make_uint4(hpack(v0.x, v0.y), hpack(v0.z, v0.w),
                      hpack(v1.x, v1.y), hpack(v1.z, v1.w));
}

// smem rings
constexpr uint32_t S1_BUF = 2 * ARR;   // Xh, Fh
constexpr uint32_t S2_BUF = 3 * ARR;   // Ph(64)+Mb(128)
constexpr int SMEM_DYN = 3 * S2_BUF;   // 82944

// ---------------------------------------------------------------------------
__global__ __launch_bounds__(256, 1) void fused_kernel(
    const float* __restrict__ a, const float* __restrict__ b,
    const float* __restrict__ feats, float* __restrict__ out)
{
    extern __shared__ char dsm[];
    const uint32_t sb = smem_u32(dsm);
    __shared__ int s_fixn;
    __shared__ unsigned int s_runid;

    const int tid = threadIdx.x;
    const int bid = blockIdx.x;
    const int lane = tid & 31;
    const int wid = tid >> 5;

    // Replay-safe run id: replays serialize, so each replay's 128 CTAs get a
    // contiguous block of arrivals.
    if (tid == 0) s_runid = atomicAdd(&g_run, 1u) / GRID;
    __syncthreads();
    const unsigned int runid = s_runid;

    const int mt1 = bid >> 2;        // 0..31  (X tile / phase-1 m-tile)
    const int nt  = bid & 3;         // 0..3   (F tile / phase-1 n-tile)
    const int qq  = bid & 3;         // quarter of the X tile this CTA converts
    const bool isA = (mt1 < 16);

    // =======================================================================
    // Phase 0: convert exactly what this CTA's cohort consumes.
    //   X tile mt1: 4 cohort CTAs convert 16 rows each.
    //   F tile nt : 32 cohort CTAs convert 2 rows each.
    // =======================================================================
    {
        const int xr0 = mt1 * 64 + qq * 16;          // 16 rows, contiguous
        const float* src = isA ? (a + (size_t)xr0 * DD)
                               : (b + (size_t)(xr0 - NA + NA - (mt1 - 16) * 64 - qq * 16
                                               + (mt1 - 16) * 64 + qq * 16 - NA + NA) * DD);
        // (simplify: b rows start at xr0 - NA)
        src = isA ? (a + (size_t)xr0 * DD) : (b + (size_t)(xr0 - NA) * DD);
        __half* dst = g_Xh + (size_t)xr0 * DD;
#pragma unroll
        for (int u = 0; u < 4; u++) {                // 1024 groups of 8 floats
            const int i = tid + u * 256;
            const size_t base = (size_t)i * 8;
            const float4 v0 = *reinterpret_cast<const float4*>(src + base);
            const float4 v1 = *reinterpret_cast<const float4*>(src + base + 4);
            *reinterpret_cast<uint4*>(dst + base) = hi4(v0, v1);
        }
        // F: 2 rows = 1024 floats = 128 groups of 8
        if (tid < 128) {
            const int fr0 = nt * 64 + mt1 * 2;
            const float* fsrc = feats + (size_t)fr0 * DD;
            __half* fdst = g_Fh + (size_t)fr0 * DD;
            const size_t base = (size_t)tid * 8;
            const float4 v0 = *reinterpret_cast<const float4*>(fsrc + base);
            const float4 v1 = *reinterpret_cast<const float4*>(fsrc + base + 4);
            *reinterpret_cast<uint4*>(fdst + base) = hi4(v0, v1);
        }
        __syncthreads();
        if (tid == 0) {
            __threadfence();
            atomicAdd(&g_cvtX[mt1], 1);
            atomicAdd(&g_cvtF[nt], 1);
        }
    }

    // =======================================================================
    // Phase 1: C = Xh · Fh^T, tile 64x64 (warp 16x32), 8 chunks, 3 buffers.
    // Waits only on its own X tile (4 producers) and F tile (32 producers).
    // =======================================================================
    {
        if (tid == 0) {
            const int tX = (int)(runid * 4u) + 4;
            const int tF = (int)(runid * 32u) + 32;
            while (ld_acq(&g_cvtX[mt1]) < tX) {}
            while (ld_acq(&g_cvtF[nt]) < tF) {}
        }
        __syncthreads();

        const int wm = wid & 3;
        const int wn = wid >> 2;
        const int m0 = mt1 * 64;
        const int n0 = nt * 64;

        const __half* pXh = g_Xh + (size_t)m0 * DD;
        const __half* pFh = g_Fh + (size_t)n0 * DD;

        if (tid == 0) s_fixn = 0;

        const int lr = tid >> 3, ls = tid & 7;
        auto load_chunk = [&](int ch, uint32_t buf) {
            const int d0 = ch * 64;
#pragma unroll
            for (int pass = 0; pass < 2; pass++) {
                const int r = lr + pass * 32;
                const size_t off = (size_t)r * DD + d0 + ls * 8;
                const uint32_t sm = buf + (uint32_t)r * TSTR + (uint32_t)(ls << 4);
                cp16(sm + 0 * ARR, pXh + off);
                cp16(sm + 1 * ARR, pFh + off);
            }
            cp_commit();
        };

        constexpr int NCH = DD / 64;
        load_chunk(0, sb);
        load_chunk(1, sb + S1_BUF);

        float acc[4][4] = {};

        for (int ch = 0; ch < NCH; ch++) {
            if (ch + 1 < NCH) cp_wait1(); else cp_wait0();
            __syncthreads();
            if (ch + 2 < NCH) load_chunk(ch + 2, sb + (uint32_t)((ch + 2) % 3) * S1_BUF);

            const uint32_t bb = sb + (uint32_t)(ch % 3) * S1_BUF;
#pragma unroll
            for (int ks = 0; ks < 4; ks++) {
                const int koff = ks * 32;
                uint32_t ah[4], fh[2][4];
                ldm_x4(ah, a_addr(bb + 0 * ARR, wm * 16, lane, koff));
#pragma unroll
                for (int p = 0; p < 2; p++)
                    ldm_x4(fh[p], b_addr(bb + 1 * ARR, wn * 32 + p * 16, lane, koff));
#pragma unroll
                for (int nti = 0; nti < 4; nti++)
                    mma_f16(acc[nti], ah, &fh[nti >> 1][(nti & 1) * 2]);
            }
        }
        __syncthreads();   // ring free; reuse dsm for fixup list

        int2* fixlist = reinterpret_cast<int2*>(dsm);

#pragma unroll
        for (int nti = 0; nti < 4; nti++)
#pragma unroll
            for (int h = 0; h < 2; h++) {
                const int grow = m0 + wm * 16 + (lane >> 2) + h * 8;
                const int col  = n0 + wn * 32 + nti * 8 + (lane & 3) * 2;
                const float v0 = acc[nti][h * 2 + 0];
                const float v1 = acc[nti][h * 2 + 1];
                if (isA) {
                    const size_t idx = (size_t)grow * KK + col;
                    *reinterpret_cast<__half2*>(g_Ph + idx) =
                        __half2(__float2half(fmaxf(v0, 0.0f)), __float2half(fmaxf(v1, 0.0f)));
                } else {
                    const int br = grow - NA;
                    const size_t idx = (size_t)br * KK + col;
                    *reinterpret_cast<__half2*>(g_Mb + idx) =
                        __half2(__float2half(v0 <= 0.0f ? 1.0f : 0.0f),
                                __float2half(v1 <= 0.0f ? 1.0f : 0.0f));
                    if (fabsf(v0) < FIXTHR) {
                        const int p = atomicAdd(&s_fixn, 1);
                        if (p < LFIXMAX) fixlist[p] = make_int2(br, col);
                    }
                    if (fabsf(v1) < FIXTHR) {
                        const int p = atomicAdd(&s_fixn, 1);
                        if (p < LFIXMAX) fixlist[p] = make_int2(br, col + 1);
                    }
                }
            }
        __syncthreads();

        // Inline exact-fp32 fixup of borderline mask entries
        if (!isA) {
            int n = s_fixn;
            if (n > LFIXMAX) n = LFIXMAX;
            for (int e = wid; e < n; e += 8) {
                const int2 rc = fixlist[e];
                const float* brp = b + (size_t)rc.x * DD;
                const float* frp = feats + (size_t)rc.y * DD;
                float s = 0.0f;
#pragma unroll
                for (int i = 0; i < 16; i++) {
                    const int idx = i * 32 + lane;
                    s = fmaf(brp[idx], frp[idx], s);
                }
#pragma unroll
                for (int o = 16; o; o >>= 1)
                    s += __shfl_xor_sync(0xFFFFFFFFu, s, o);
                if (lane == 0)
                    g_Mb[(size_t)rc.x * KK + rc.y] = __float2half(s <= 0.0f ? 1.0f : 0.0f);
            }
        }
        __syncthreads();

        if (tid == 0) {
            __threadfence();
            if (isA) atomicAdd(&g_rdyP[mt1], 1);
            else     atomicAdd(&g_rdyM[mt1 - 16], 1);
        }
    }

    // =======================================================================
    // Phase 2: out = Ph · Mb^T, tile 64x128 (warp 32x32), 4 chunks, 3 bufs.
    // =======================================================================
    {
        const int it = bid >> 3;
        const int jt = (bid & 7) * 2;
        const int i0 = it * 64;
        const int j0 = (bid & 7) * 128;

        if (tid == 0) {
            const int tgt = (int)(runid * 4u) + 4;
            while (ld_acq(&g_rdyP[it]) < tgt) {}
            while (ld_acq(&g_rdyM[jt]) < tgt) {}
            while (ld_acq(&g_rdyM[jt + 1]) < tgt) {}
        }
        __syncthreads();

        const __half* pPh = g_Ph + (size_t)i0 * KK;
        const __half* pMb = g_Mb + (size_t)j0 * KK;

        const int lr = tid >> 3, ls = tid & 7;
        auto load_chunk = [&](int ch, uint32_t buf) {
            const int k0 = ch * 64;
#pragma unroll
            for (int pass = 0; pass < 2; pass++) {
                const int r = lr + pass * 32;
                cp16(buf + (uint32_t)r * TSTR + (uint32_t)(ls << 4),
                     pPh + (size_t)r * KK + k0 + ls * 8);
            }
#pragma unroll
            for (int pass = 0; pass < 4; pass++) {
                const int r = lr + pass * 32;
                cp16(buf + ARR + (uint32_t)r * TSTR + (uint32_t)(ls << 4),
                     pMb + (size_t)r * KK + k0 + ls * 8);
            }
            cp_commit();
        };

        const int wm = wid & 1;
        const int wn = wid >> 1;

        constexpr int NCH = KK / 64;
        load_chunk(0, sb);
        load_chunk(1, sb + S2_BUF);

        float acc[2][4][4] = {};

        for (int ch = 0; ch < NCH; ch++) {
            if (ch + 1 < NCH) cp_wait1(); else cp_wait0();
            __syncthreads();
            if (ch + 2 < NCH) load_chunk(ch + 2, sb + (uint32_t)((ch + 2) % 3) * S2_BUF);

            const uint32_t bb = sb + (uint32_t)(ch % 3) * S2_BUF;
#pragma unroll
            for (int ks = 0; ks < 4; ks++) {
                const int koff = ks * 32;
                uint32_t ph[2][4], mb[2][4];
#pragma unroll
                for (int mt = 0; mt < 2; mt++)
                    ldm_x4(ph[mt], a_addr(bb, wm * 32 + mt * 16, lane, koff));
#pragma unroll
                for (int p = 0; p < 2; p++)
                    ldm_x4(mb[p], b_addr(bb + ARR, wn * 32 + p * 16, lane, koff));
#pragma unroll
                for (int mt = 0; mt < 2; mt++)
#pragma unroll
                    for (int nti = 0; nti < 4; nti++)
                        mma_f16(acc[mt][nti], ph[mt], &mb[nti >> 1][(nti & 1) * 2]);
            }
        }

#pragma unroll
        for (int mt = 0; mt < 2; mt++)
#pragma unroll
            for (int nti = 0; nti < 4; nti++)
#pragma unroll
                for (int h = 0; h < 2; h++) {
                    const int row = i0 + wm * 32 + mt * 16 + (lane >> 2) + h * 8;
                    const int col = j0 + wn * 32 + nti * 8 + (lane & 3) * 2;
                    *reinterpret_cast<float2*>(out + (size_t)row * NB + col) =
                        make_float2(acc[mt][nti][h * 2 + 0], acc[mt][nti][h * 2 + 1]);
                }
    }
}

// ---------------------------------------------------------------------------
extern "C" void kernel_launch(void* const* d_in, const int* in_sizes, int n_in,
                              void* d_out, int out_size)
{
    const float* a     = (const float*)d_in[0];
    const float* b     = (const float*)d_in[1];
    const float* feats = (const float*)d_in[2];
    float* out = (float*)d_out;
    (void)in_sizes; (void)n_in; (void)out_size;

    cudaFuncSetAttribute(fused_kernel, cudaFuncAttributeMaxDynamicSharedMemorySize, SMEM_DYN);
    fused_kernel<<<GRID, 256, SMEM_DYN>>>(a, b, feats, out);
}

// round 16
// speedup vs baseline: 1.4349x; 1.4349x over previous
#include <cuda_runtime.h>
#include <cuda_fp16.h>
#include <cstdint>

constexpr int NA = 1024, NB = 1024, DD = 512, KK = 256;
constexpr unsigned int GRID = 128;

// Device scratch
__device__ __half g_Xh[(NA + NB) * DD];
__device__ __half g_Fh[KK * DD];
__device__ __half g_Ph[NA * KK];
__device__ __half g_Mb[NB * KK];
__device__ unsigned int g_bar_cnt;    // monotonic, replay-safe
__device__ int g_rdyP[16];            // per 64-row Ph tile: 4 producers
__device__ int g_rdyM[16];            // per 64-row Mb tile: 4 producers
constexpr float FIXTHR = 0.25f;
constexpr int LFIXMAX = 512;

// ---------------------------------------------------------------------------
__device__ __forceinline__ uint32_t smem_u32(const void* p) {
    uint32_t r;
    asm("{ .reg .u64 t; cvta.to.shared.u64 t, %1; cvt.u32.u64 %0, t; }" : "=r"(r) : "l"(p));
    return r;
}
__device__ __forceinline__ void cp16(uint32_t dst, const void* src) {
    asm volatile("cp.async.cg.shared.global [%0], [%1], 16;" :: "r"(dst), "l"(src) : "memory");
}
__device__ __forceinline__ void cp_commit() { asm volatile("cp.async.commit_group;" ::: "memory"); }
__device__ __forceinline__ void cp_wait1()  { asm volatile("cp.async.wait_group 1;" ::: "memory"); }
__device__ __forceinline__ void cp_wait0()  { asm volatile("cp.async.wait_group 0;" ::: "memory"); }

__device__ __forceinline__ void ldm_x4(uint32_t* r, uint32_t addr) {
    asm volatile("ldmatrix.sync.aligned.m8n8.x4.shared.b16 {%0,%1,%2,%3}, [%4];"
                 : "=r"(r[0]), "=r"(r[1]), "=r"(r[2]), "=r"(r[3]) : "r"(addr));
}
__device__ __forceinline__ void mma_f16(float* d, const uint32_t* a, const uint32_t* b) {
    asm volatile(
        "mma.sync.aligned.m16n8k16.row.col.f32.f16.f16.f32 "
        "{%0,%1,%2,%3}, {%4,%5,%6,%7}, {%8,%9}, {%0,%1,%2,%3};"
        : "+f"(d[0]), "+f"(d[1]), "+f"(d[2]), "+f"(d[3])
        : "r"(a[0]), "r"(a[1]), "r"(a[2]), "r"(a[3]), "r"(b[0]), "r"(b[1]));
}

// Parametric ldmatrix addressing (stride = bytes per row; stride%128==16 -> conflict-free)
__device__ __forceinline__ uint32_t a_addr(uint32_t base, int row0, int lane, int koff, uint32_t stride) {
    return base + (uint32_t)(row0 + (lane & 15)) * stride + (uint32_t)koff + ((lane >> 4) << 4);
}
__device__ __forceinline__ uint32_t b_addr(uint32_t base, int row0, int lane, int koff, uint32_t stride) {
    return base + (uint32_t)(row0 + (lane & 7) + ((lane >> 4) << 3)) * stride
                + (uint32_t)koff + (((lane >> 3) & 1) << 4);
}

// Grid barrier (128 CTAs, 1/SM, co-resident; monotonic counter, replay-safe)
__device__ __forceinline__ void grid_barrier() {
    __syncthreads();
    if (threadIdx.x == 0) {
        __threadfence();
        const unsigned int arrival = atomicAdd(&g_bar_cnt, 1u);
        const unsigned int target = (arrival / GRID + 1u) * GRID;
        unsigned int v;
        do {
            asm volatile("ld.acquire.gpu.u32 %0, [%1];" : "=r"(v) : "l"(&g_bar_cnt));
        } while (v < target);
    }
    __syncthreads();
}
__device__ __forceinline__ int ld_acq(const int* p) {
    int v;
    asm volatile("ld.acquire.gpu.s32 %0, [%1];" : "=r"(v) : "l"(p));
    return v;
}

__device__ __forceinline__ uint32_t hpack(float x, float y) {
    __half2 t = __float22half2_rn(make_float2(x, y));
    return *reinterpret_cast<uint32_t*>(&t);
}
__device__ __forceinline__ uint4 hi4(const float4& v0, const float4& v1) {
    return make_uint4(hpack(v0.x, v0.y), hpack(v0.z, v0.w),
                      hpack(v1.x, v1.y), hpack(v1.z, v1.w));
}

// smem geometry
constexpr uint32_t TSTR1 = 272;            // phase 1: 128 fp16 = 256B + 16B pad
constexpr uint32_t ARR1  = 64 * TSTR1;     // 17408
constexpr uint32_t S1_BUF = 2 * ARR1;      // Xh + Fh = 34816
constexpr uint32_t TSTR2 = 528;            // phase 2: 256 fp16 = 512B + 16B pad
constexpr uint32_t S2_PH = 0;
constexpr uint32_t S2_MB = 64 * TSTR2;     // 33792
constexpr int SMEM_DYN = 3 * S1_BUF;       // 104448 (> 101376 phase-2 need)

// ---------------------------------------------------------------------------
__global__ __launch_bounds__(256, 1) void fused_kernel(
    const float* __restrict__ a, const float* __restrict__ b,
    const float* __restrict__ feats, float* __restrict__ out)
{
    extern __shared__ char dsm[];
    const uint32_t sb = smem_u32(dsm);
    __shared__ int s_fixn;

    const int tid = threadIdx.x;
    const int bid = blockIdx.x;
    const int lane = tid & 31;
    const int wid = tid >> 5;
    const int gt = bid * 256 + tid;      // 0..32767

    // =======================================================================
    // Phase 0: reset flags (bid 0) + convert hi-only.
    // =======================================================================
    if (bid == 0 && tid < 32) {
        if (tid < 16) g_rdyP[tid] = 0;
        else          g_rdyM[tid - 16] = 0;
    }
    {
#pragma unroll
        for (int k = 0; k < 2; k++) {
            const int base = (gt + k * 32768) * 8;
            const float4 v0 = *reinterpret_cast<const float4*>(a + base);
            const float4 v1 = *reinterpret_cast<const float4*>(a + base + 4);
            *reinterpret_cast<uint4*>(g_Xh + base) = hi4(v0, v1);
        }
#pragma unroll
        for (int k = 0; k < 2; k++) {
            const int base = (gt + k * 32768) * 8;
            const float4 v0 = *reinterpret_cast<const float4*>(b + base);
            const float4 v1 = *reinterpret_cast<const float4*>(b + base + 4);
            *reinterpret_cast<uint4*>(g_Xh + NA * DD + base) = hi4(v0, v1);
        }
        if (gt < 16384) {
            const int base = gt * 8;
            const float4 v0 = *reinterpret_cast<const float4*>(feats + base);
            const float4 v1 = *reinterpret_cast<const float4*>(feats + base + 4);
            *reinterpret_cast<uint4*>(g_Fh + base) = hi4(v0, v1);
        }
    }

    grid_barrier();   // ONLY grid barrier

    // =======================================================================
    // Phase 1: C = Xh · Fh^T, tile 64x64 (warp 16x32), k-chunk 128 (4 chunks),
    // 3-buffer ring. Epilogue + inline fixup + ready publish.
    // =======================================================================
    {
        const int wm = wid & 3;
        const int wn = wid >> 2;
        const int mt1 = bid >> 2;        // 0..31
        const int m0 = mt1 * 64;
        const int n0 = (bid & 3) * 64;
        const bool isA = (m0 < NA);

        const __half* pXh = g_Xh + (size_t)m0 * DD;
        const __half* pFh = g_Fh + (size_t)n0 * DD;

        if (tid == 0) s_fixn = 0;

        auto load_chunk = [&](int ch, uint32_t buf) {
            const int d0 = ch * 128;
            // X: 64 rows x 16 slots(16B) = 1024 cp -> 4/thread; F same.
#pragma unroll
            for (int u = 0; u < 4; u++) {
                const int v = tid + u * 256;
                const int r = v >> 4, s = v & 15;
                const size_t off = (size_t)r * DD + d0 + s * 8;
                const uint32_t sm = buf + (uint32_t)r * TSTR1 + (uint32_t)(s << 4);
                cp16(sm,        pXh + off);
                cp16(sm + ARR1, pFh + off);
            }
            cp_commit();
        };

        constexpr int NCH = DD / 128;   // 4
        load_chunk(0, sb);
        load_chunk(1, sb + S1_BUF);

        float acc[4][4] = {};

        for (int ch = 0; ch < NCH; ch++) {
            if (ch + 1 < NCH) cp_wait1(); else cp_wait0();
            __syncthreads();
            if (ch + 2 < NCH) load_chunk(ch + 2, sb + (uint32_t)((ch + 2) % 3) * S1_BUF);

            const uint32_t bb = sb + (uint32_t)(ch % 3) * S1_BUF;
#pragma unroll
            for (int ks = 0; ks < 8; ks++) {
                const int koff = ks * 32;
                uint32_t ah[4], fh[2][4];
                ldm_x4(ah, a_addr(bb, wm * 16, lane, koff, TSTR1));
#pragma unroll
                for (int p = 0; p < 2; p++)
                    ldm_x4(fh[p], b_addr(bb + ARR1, wn * 32 + p * 16, lane, koff, TSTR1));
#pragma unroll
                for (int nt = 0; nt < 4; nt++)
                    mma_f16(acc[nt], ah, &fh[nt >> 1][(nt & 1) * 2]);
            }
        }
        __syncthreads();   // ring free; reuse dsm for fixup list

        int2* fixlist = reinterpret_cast<int2*>(dsm);

#pragma unroll
        for (int nt = 0; nt < 4; nt++)
#pragma unroll
            for (int h = 0; h < 2; h++) {
                const int grow = m0 + wm * 16 + (lane >> 2) + h * 8;
                const int col  = n0 + wn * 32 + nt * 8 + (lane & 3) * 2;
                const float v0 = acc[nt][h * 2 + 0];
                const float v1 = acc[nt][h * 2 + 1];
                if (isA) {
                    const size_t idx = (size_t)grow * KK + col;
                    *reinterpret_cast<__half2*>(g_Ph + idx) =
                        __half2(__float2half(fmaxf(v0, 0.0f)), __float2half(fmaxf(v1, 0.0f)));
                } else {
                    const int br = grow - NA;
                    const size_t idx = (size_t)br * KK + col;
                    *reinterpret_cast<__half2*>(g_Mb + idx) =
                        __half2(__float2half(v0 <= 0.0f ? 1.0f : 0.0f),
                                __float2half(v1 <= 0.0f ? 1.0f : 0.0f));
                    if (fabsf(v0) < FIXTHR) {
                        const int p = atomicAdd(&s_fixn, 1);
                        if (p < LFIXMAX) fixlist[p] = make_int2(br, col);
                    }
                    if (fabsf(v1) < FIXTHR) {
                        const int p = atomicAdd(&s_fixn, 1);
                        if (p < LFIXMAX) fixlist[p] = make_int2(br, col + 1);
                    }
                }
            }
        __syncthreads();

        // Inline exact-fp32 fixup of borderline mask entries
        if (!isA) {
            int n = s_fixn;
            if (n > LFIXMAX) n = LFIXMAX;
            for (int e = wid; e < n; e += 8) {
                const int2 rc = fixlist[e];
                const float* brp = b + (size_t)rc.x * DD;
                const float* frp = feats + (size_t)rc.y * DD;
                float s = 0.0f;
#pragma unroll
                for (int i = 0; i < 16; i++) {
                    const int idx = i * 32 + lane;
                    s = fmaf(brp[idx], frp[idx], s);
                }
#pragma unroll
                for (int o = 16; o; o >>= 1)
                    s += __shfl_xor_sync(0xFFFFFFFFu, s, o);
                if (lane == 0)
                    g_Mb[(size_t)rc.x * KK + rc.y] = __float2half(s <= 0.0f ? 1.0f : 0.0f);
            }
        }
        __syncthreads();

        if (tid == 0) {
            __threadfence();
            if (isA) atomicAdd(&g_rdyP[mt1], 1);
            else     atomicAdd(&g_rdyM[mt1 - 16], 1);
        }
    }

    // =======================================================================
    // Phase 2: out = Ph · Mb^T, tile 64x128 (warp 32x32), MONOLITHIC K=256.
    // One cp.async burst, one sync, 16 straight-line ks steps.
    // =======================================================================
    {
        const int it = bid >> 3;
        const int jt = (bid & 7) * 2;
        const int i0 = it * 64;
        const int j0 = (bid & 7) * 128;

        if (tid == 0) {
            while (ld_acq(&g_rdyP[it]) < 4) {}
            while (ld_acq(&g_rdyM[jt]) < 4) {}
            while (ld_acq(&g_rdyM[jt + 1]) < 4) {}
        }
        __syncthreads();

        const __half* pPh = g_Ph + (size_t)i0 * KK;
        const __half* pMb = g_Mb + (size_t)j0 * KK;

        // Load: Ph 64 rows x 32 slots = 2048 cp; Mb 128 x 32 = 4096 cp.
        for (int v = tid; v < 6144; v += 256) {
            if (v < 2048) {
                const int r = v >> 5, s = v & 31;
                cp16(sb + S2_PH + (uint32_t)r * TSTR2 + (uint32_t)(s << 4),
                     pPh + (size_t)r * KK + s * 8);
            } else {
                const int w = v - 2048, r = w >> 5, s = w & 31;
                cp16(sb + S2_MB + (uint32_t)r * TSTR2 + (uint32_t)(s << 4),
                     pMb + (size_t)r * KK + s * 8);
            }
        }
        cp_commit();
        cp_wait0();
        __syncthreads();

        const int wm = wid & 1;
        const int wn = wid >> 1;

        float acc[2][4][4] = {};

#pragma unroll
        for (int ks = 0; ks < 16; ks++) {
            const int koff = ks * 32;
            uint32_t ph[2][4], mb[2][4];
#pragma unroll
            for (int mt = 0; mt < 2; mt++)
                ldm_x4(ph[mt], a_addr(sb + S2_PH, wm * 32 + mt * 16, lane, koff, TSTR2));
#pragma unroll
            for (int p = 0; p < 2; p++)
                ldm_x4(mb[p], b_addr(sb + S2_MB, wn * 32 + p * 16, lane, koff, TSTR2));
#pragma unroll
            for (int mt = 0; mt < 2; mt++)
#pragma unroll
                for (int nt = 0; nt < 4; nt++)
                    mma_f16(acc[mt][nt], ph[mt], &mb[nt >> 1][(nt & 1) * 2]);
        }

#pragma unroll
        for (int mt = 0; mt < 2; mt++)
#pragma unroll
            for (int nt = 0; nt < 4; nt++)
#pragma unroll
                for (int h = 0; h < 2; h++) {
                    const int row = i0 + wm * 32 + mt * 16 + (lane >> 2) + h * 8;
                    const int col = j0 + wn * 32 + nt * 8 + (lane & 3) * 2;
                    *reinterpret_cast<float2*>(out + (size_t)row * NB + col) =
                        make_float2(acc[mt][nt][h * 2 + 0], acc[mt][nt][h * 2 + 1]);
                }
    }
}

// ---------------------------------------------------------------------------
extern "C" void kernel_launch(void* const* d_in, const int* in_sizes, int n_in,
                              void* d_out, int out_size)
{
    const float* a     = (const float*)d_in[0];
    const float* b     = (const float*)d_in[1];
    const float* feats = (const float*)d_in[2];
    float* out = (float*)d_out;
    (void)in_sizes; (void)n_in; (void)out_size;

    cudaFuncSetAttribute(fused_kernel, cudaFuncAttributeMaxDynamicSharedMemorySize, SMEM_DYN);
    fused_kernel<<<GRID, 256, SMEM_DYN>>>(a, b, feats, out);
}